// round 14
// baseline (speedup 1.0000x reference)
#include <cuda_runtime.h>
#include <cuda_bf16.h>
#include <cuda_fp16.h>
#include <math.h>
#include <stdint.h>

#define D 128
#define NF_MAX 50000
#define NP_MAX 12500
#define EF_MAX 600000

// ---------------- scratch (static device globals) ----------------
__device__ __half g_h1[(size_t)NF_MAX * D];   // GEMM0 out (np rows) then fused1 out (nf rows)
__device__ __half g_h2[(size_t)NP_MAX * D];   // fused0 out (compact np)
__device__ int    g_cntf[NF_MAX];
__device__ int    g_rpf[NF_MAX + 1];
__device__ int    g_curf[NF_MAX];
__device__ int    g_esrcf[EF_MAX];
__device__ float  g_dinvf[NF_MAX];
__device__ int    g_cntp[NP_MAX];
__device__ int    g_rpp[NP_MAX + 1];
__device__ int    g_curp[NP_MAX];
__device__ int    g_esrcp[EF_MAX / 4];
__device__ float  g_dinvp[NP_MAX];
__device__ int    g_inv[NF_MAX];
__device__ int    g_bsf[64];
__device__ int    g_bsp[64];
__device__ unsigned char g_wimg[3][2][32768];

static inline int cdiv(int a, int b) { return (a + b - 1) / b; }

__host__ __device__ __forceinline__ uint32_t swz(int row, int kbyte) {
    return (uint32_t)(row * 256 + (kbyte ^ ((row & 7) << 4)));
}

__device__ __forceinline__ uint32_t smem_u32(const void* p) {
    uint32_t a;
    asm("{ .reg .u64 t; cvta.to.shared.u64 t, %1; cvt.u32.u64 %0, t; }" : "=r"(a) : "l"(p));
    return a;
}
__device__ __forceinline__ void ldmx4(uint32_t* r, uint32_t addr) {
    asm volatile("ldmatrix.sync.aligned.m8n8.x4.shared.b16 {%0,%1,%2,%3}, [%4];"
                 : "=r"(r[0]), "=r"(r[1]), "=r"(r[2]), "=r"(r[3]) : "r"(addr));
}
__device__ __forceinline__ void mma16816(float* c, const uint32_t* a, uint32_t b0, uint32_t b1) {
    asm volatile("mma.sync.aligned.m16n8k16.row.col.f32.bf16.bf16.f32 "
                 "{%0,%1,%2,%3}, {%4,%5,%6,%7}, {%8,%9}, {%0,%1,%2,%3};"
                 : "+f"(c[0]), "+f"(c[1]), "+f"(c[2]), "+f"(c[3])
                 : "r"(a[0]), "r"(a[1]), "r"(a[2]), "r"(a[3]), "r"(b0), "r"(b1));
}
__device__ __forceinline__ void bf16split2(float a0, float a1, uint32_t& uhi, uint32_t& ulo) {
    __nv_bfloat16 h0 = __float2bfloat16(a0), h1 = __float2bfloat16(a1);
    float r0 = a0 - __bfloat162float(h0);
    float r1 = a1 - __bfloat162float(h1);
    __nv_bfloat16 l0 = __float2bfloat16(r0), l1 = __float2bfloat16(r1);
    uhi = (uint32_t)__bfloat16_as_ushort(h0) | ((uint32_t)__bfloat16_as_ushort(h1) << 16);
    ulo = (uint32_t)__bfloat16_as_ushort(l0) | ((uint32_t)__bfloat16_as_ushort(l1) << 16);
}

// ================= fused zero + W-prep =================
__global__ void k_zero_prep(int* cntf, int* cntp, int* inv, int nf, int np,
                            const float* __restrict__ W0, const float* __restrict__ W1,
                            const float* __restrict__ W2) {
    int i = blockIdx.x * blockDim.x + threadIdx.x;
    if (i < nf) { cntf[i] = 0; inv[i] = -1; }
    if (i < np) cntp[i] = 0;
    if (i < 3 * 128 * 128) {
        int w = i >> 14, rem = i & 16383;
        int k = rem >> 7, n = rem & 127;
        const float* W = (w == 0) ? W0 : (w == 1) ? W1 : W2;
        float v = W[k * 128 + n];
        uint32_t uhi, ulo;
        __nv_bfloat16 hb = __float2bfloat16(v);
        float r = v - __bfloat162float(hb);
        __nv_bfloat16 lb = __float2bfloat16(r);
        uint32_t sw = swz(n, k * 2);
        *(unsigned short*)(&g_wimg[w][0][sw]) = __bfloat16_as_ushort(hb);
        *(unsigned short*)(&g_wimg[w][1][sw]) = __bfloat16_as_ushort(lb);
        (void)uhi; (void)ulo;
    }
}

__global__ void k_inv(const int* __restrict__ unpool, int* __restrict__ inv, int np) {
    int r = blockIdx.x * blockDim.x + threadIdx.x;
    if (r < np) inv[unpool[r]] = r;
}

// ================= single-graph CSR kernels =================
__global__ void k_hist(const int* __restrict__ dst, int E, int* __restrict__ cnt) {
    int e = blockIdx.x * blockDim.x + threadIdx.x;
    if (e < E) atomicAdd(&cnt[dst[e]], 1);
}

__global__ void k_bsum(const int* __restrict__ cnt, int n, int* __restrict__ bs) {
    int b = blockIdx.x;
    int tid = threadIdx.x, lane = tid & 31, warp = tid >> 5;
    int i0 = b * 1024 + tid * 4;
    int s = 0;
#pragma unroll
    for (int k = 0; k < 4; k++) if (i0 + k < n) s += cnt[i0 + k];
#pragma unroll
    for (int off = 16; off > 0; off >>= 1) s += __shfl_down_sync(0xffffffffu, s, off);
    __shared__ int ws[8];
    if (lane == 0) ws[warp] = s;
    __syncthreads();
    if (tid == 0) {
        int t = 0;
#pragma unroll
        for (int w = 0; w < 8; w++) t += ws[w];
        bs[b] = t;
    }
}

__global__ void k_write(const int* __restrict__ cnt, int n, const int* __restrict__ bs, int nb,
                        int* __restrict__ rp, int* __restrict__ cur, float* __restrict__ dinv) {
    __shared__ int sbs[64];
    __shared__ int ws[8];
    int b = blockIdx.x;
    int tid = threadIdx.x, lane = tid & 31, warp = tid >> 5;
    if (tid < 64) sbs[tid] = (tid < nb) ? bs[tid] : 0;
    __syncthreads();
#pragma unroll
    for (int off = 1; off < 64; off <<= 1) {
        int add = (tid >= off && tid < 64) ? sbs[tid - off] : 0;
        __syncthreads();
        if (tid < 64) sbs[tid] += add;
        __syncthreads();
    }
    int i0 = b * 1024 + tid * 4;
    int v[4];
#pragma unroll
    for (int k = 0; k < 4; k++) v[k] = (i0 + k < n) ? cnt[i0 + k] : 0;
    int s = v[0] + v[1] + v[2] + v[3];
    int inc = s;
#pragma unroll
    for (int off = 1; off < 32; off <<= 1) {
        int u = __shfl_up_sync(0xffffffffu, inc, off);
        if (lane >= off) inc += u;
    }
    if (lane == 31) ws[warp] = inc;
    __syncthreads();
    int woff = 0;
#pragma unroll
    for (int w = 0; w < 8; w++) if (w < warp) woff += ws[w];
    int blockoff = b ? sbs[b - 1] : 0;
    int pre = blockoff + woff + inc - s;
#pragma unroll
    for (int k = 0; k < 4; k++) {
        int i = i0 + k;
        if (i < n) {
            rp[i] = pre; cur[i] = pre;
            dinv[i] = rsqrtf((float)v[k] + 1.0f);
            pre += v[k];
        }
    }
    if (b == 0 && tid == 0) rp[n] = sbs[63];
}

__global__ void k_place(const int* __restrict__ src, const int* __restrict__ dst, int E,
                        int* __restrict__ cur, int* __restrict__ esrc) {
    int e = blockIdx.x * blockDim.x + threadIdx.x;
    if (e < E) {
        int p = atomicAdd(&cur[dst[e]], 1);
        esrc[p] = src[e];
    }
}

// ================= GEMM (M=64, fp32 A input) for GEMM0 =================
__global__ void __launch_bounds__(256) k_gemm_mma(
    const float* __restrict__ A, const unsigned char* __restrict__ Whi,
    const unsigned char* __restrict__ Wlo, __half* __restrict__ C, int n) {
    extern __shared__ unsigned char sm[];
    const int OFF_AHI = 0, OFF_ALO = 16384, OFF_BHI = 32768, OFF_BLO = 65536;
    const uint32_t smb = smem_u32(sm);
    const int tid = threadIdx.x, wid = tid >> 5, lane = tid & 31;
    const int row0 = blockIdx.x * 64;

    for (int i = tid; i < 2048; i += 256) {
        ((float4*)(sm + OFF_BHI))[i] = ((const float4*)Whi)[i];
        ((float4*)(sm + OFF_BLO))[i] = ((const float4*)Wlo)[i];
    }
    {
        int row = tid >> 2, quarter = tid & 3;
        int gr = row0 + row;
        const float4* Arow = (const float4*)(A + (size_t)gr * D) + quarter * 8;
        unsigned char* ahi = sm + OFF_AHI;
        unsigned char* alo = sm + OFF_ALO;
#pragma unroll
        for (int q = 0; q < 8; q++) {
            float4 v = (gr < n) ? Arow[q] : make_float4(0.f, 0.f, 0.f, 0.f);
            float f[4] = {v.x, v.y, v.z, v.w};
#pragma unroll
            for (int p = 0; p < 2; p++) {
                uint32_t uhi, ulo;
                bf16split2(f[p * 2], f[p * 2 + 1], uhi, ulo);
                int k = quarter * 32 + q * 4 + p * 2;
                uint32_t sw = swz(row, k * 2);
                *(uint32_t*)(ahi + sw) = uhi;
                *(uint32_t*)(alo + sw) = ulo;
            }
        }
    }
    __syncthreads();

    const int rg = wid & 3, ch = wid >> 2;
    const int m0 = rg * 16;
    float acc[8][4];
#pragma unroll
    for (int t = 0; t < 8; t++)
#pragma unroll
        for (int q = 0; q < 4; q++) acc[t][q] = 0.f;

    const int a_row = m0 + (lane & 15);
    const uint32_t a_base = smb + (uint32_t)(a_row * 256);
    const int a_swrow = (a_row & 7) << 4;
    const int a_kadd = (lane >> 4) * 16;
    const int b_rowoff = (lane & 7) + (lane >> 4) * 8;
    const int b_kadd = ((lane >> 3) & 1) * 16;

#pragma unroll 2
    for (int k0 = 0; k0 < 8; k0++) {
        const int kb = k0 * 32;
        uint32_t ahi[4], alo[4];
        uint32_t a_off = (uint32_t)((kb + a_kadd) ^ a_swrow);
        ldmx4(ahi, a_base + OFF_AHI + a_off);
        ldmx4(alo, a_base + OFF_ALO + a_off);
#pragma unroll
        for (int ntp = 0; ntp < 4; ntp++) {
            const int n0 = ch * 64 + ntp * 16;
            const int b_row = n0 + b_rowoff;
            uint32_t b_off = (uint32_t)(b_row * 256 + ((kb + b_kadd) ^ ((b_row & 7) << 4)));
            uint32_t bh[4], bl[4];
            ldmx4(bh, smb + OFF_BHI + b_off);
            ldmx4(bl, smb + OFF_BLO + b_off);
            mma16816(acc[2 * ntp],     ahi, bh[0], bh[1]);
            mma16816(acc[2 * ntp + 1], ahi, bh[2], bh[3]);
            mma16816(acc[2 * ntp],     ahi, bl[0], bl[1]);
            mma16816(acc[2 * ntp + 1], ahi, bl[2], bl[3]);
            mma16816(acc[2 * ntp],     alo, bh[0], bh[1]);
            mma16816(acc[2 * ntp + 1], alo, bh[2], bh[3]);
        }
    }

    const int r_lo = row0 + m0 + (lane >> 2);
    const int cbase = ch * 64 + (lane & 3) * 2;
    if (r_lo < n) {
        __half* crow = C + (size_t)r_lo * D;
#pragma unroll
        for (int t = 0; t < 8; t++)
            *(__half2*)(crow + cbase + t * 8) = __floats2half2_rn(acc[t][0], acc[t][1]);
    }
    const int r_hi = r_lo + 8;
    if (r_hi < n) {
        __half* crow = C + (size_t)r_hi * D;
#pragma unroll
        for (int t = 0; t < 8; t++)
            *(__half2*)(crow + cbase + t * 8) = __floats2half2_rn(acc[t][2], acc[t][3]);
    }
}

// ================= FUSED gather + GEMM (64 rows/block) =================
// perEdge != 0: edge weight = dinv[s]*dinv[row] (conv0; inv unused/null).
// perEdge == 0: sources pre-scaled; result = (Σ + self) * dinv[row]; inv maps src->compact.
// After gather: +bias, ELU, bf16-split into A tile; then MMA with W; epilogue scale ->half out.
__global__ void __launch_bounds__(256) k_gather_gemm(
    const int* __restrict__ rp, const int* __restrict__ esrc,
    const float* __restrict__ dinv, const __half* __restrict__ xw,
    const float* __restrict__ bias, const int* __restrict__ inv, int perEdge,
    const unsigned char* __restrict__ Whi, const unsigned char* __restrict__ Wlo,
    __half* __restrict__ C, int n,
    const float* __restrict__ scale, const int* __restrict__ smap) {
    extern __shared__ unsigned char sm[];
    const int OFF_AHI = 0, OFF_ALO = 16384, OFF_BHI = 32768, OFF_BLO = 65536;
    const uint32_t smb = smem_u32(sm);
    const int tid = threadIdx.x, wid = tid >> 5, lane = tid & 31;
    const int row0 = blockIdx.x * 64;

    for (int i = tid; i < 2048; i += 256) {
        ((float4*)(sm + OFF_BHI))[i] = ((const float4*)Whi)[i];
        ((float4*)(sm + OFF_BLO))[i] = ((const float4*)Wlo)[i];
    }

    float4 bb = reinterpret_cast<const float4*>(bias)[lane];
    unsigned char* ahi = sm + OFF_AHI;
    unsigned char* alo = sm + OFF_ALO;

    // gather phase: warp handles local rows wid*8 .. wid*8+7
#pragma unroll 1
    for (int rr = 0; rr < 8; rr++) {
        int lrow = wid * 8 + rr;
        int row = row0 + lrow;
        float4 acc = make_float4(0.f, 0.f, 0.f, 0.f);
        if (row < n) {
            float di = dinv[row];
            // self loop
            {
                int sr = inv ? inv[row] : row;
                if (sr >= 0) {
                    uint2 u = reinterpret_cast<const uint2*>(xw + (size_t)sr * D)[lane];
                    float2 f0 = __half22float2(*reinterpret_cast<__half2*>(&u.x));
                    float2 f1 = __half22float2(*reinterpret_cast<__half2*>(&u.y));
                    float w = perEdge ? di * di : 1.0f;
                    acc.x = f0.x * w; acc.y = f0.y * w; acc.z = f1.x * w; acc.w = f1.y * w;
                }
            }
            int s0 = rp[row], s1 = rp[row + 1];
            for (int base = s0; base < s1; base += 32) {
                int cnt = min(32, s1 - base);
                int sid = -1; float dv = 1.f;
                if (lane < cnt) {
                    int s = esrc[base + lane];
                    if (perEdge) dv = dinv[s];
                    sid = inv ? inv[s] : s;
                }
                for (int j = 0; j < cnt; j++) {
                    int s = __shfl_sync(0xffffffffu, sid, j);
                    float w = perEdge ? __shfl_sync(0xffffffffu, dv, j) * di : 1.0f;
                    if (s < 0) continue;
                    uint2 u = reinterpret_cast<const uint2*>(xw + (size_t)s * D)[lane];
                    float2 f0 = __half22float2(*reinterpret_cast<__half2*>(&u.x));
                    float2 f1 = __half22float2(*reinterpret_cast<__half2*>(&u.y));
                    acc.x += f0.x * w; acc.y += f0.y * w; acc.z += f1.x * w; acc.w += f1.y * w;
                }
            }
            if (!perEdge) { acc.x *= di; acc.y *= di; acc.z *= di; acc.w *= di; }
            acc.x += bb.x; acc.y += bb.y; acc.z += bb.z; acc.w += bb.w;
            acc.x = acc.x > 0.f ? acc.x : expm1f(acc.x);
            acc.y = acc.y > 0.f ? acc.y : expm1f(acc.y);
            acc.z = acc.z > 0.f ? acc.z : expm1f(acc.z);
            acc.w = acc.w > 0.f ? acc.w : expm1f(acc.w);
        }
        // bf16-split into swizzled A tile (cols lane*4 .. lane*4+3)
        uint32_t uhi0, ulo0, uhi1, ulo1;
        bf16split2(acc.x, acc.y, uhi0, ulo0);
        bf16split2(acc.z, acc.w, uhi1, ulo1);
        uint32_t sw0 = swz(lrow, lane * 8);
        uint32_t sw1 = swz(lrow, lane * 8 + 4);
        *(uint32_t*)(ahi + sw0) = uhi0;
        *(uint32_t*)(alo + sw0) = ulo0;
        *(uint32_t*)(ahi + sw1) = uhi1;
        *(uint32_t*)(alo + sw1) = ulo1;
    }
    __syncthreads();

    // MMA phase
    const int rg = wid & 3, ch = wid >> 2;
    const int m0 = rg * 16;
    float acc[8][4];
#pragma unroll
    for (int t = 0; t < 8; t++)
#pragma unroll
        for (int q = 0; q < 4; q++) acc[t][q] = 0.f;

    const int a_row = m0 + (lane & 15);
    const uint32_t a_base = smb + (uint32_t)(a_row * 256);
    const int a_swrow = (a_row & 7) << 4;
    const int a_kadd = (lane >> 4) * 16;
    const int b_rowoff = (lane & 7) + (lane >> 4) * 8;
    const int b_kadd = ((lane >> 3) & 1) * 16;

#pragma unroll 2
    for (int k0 = 0; k0 < 8; k0++) {
        const int kb = k0 * 32;
        uint32_t ahr[4], alr[4];
        uint32_t a_off = (uint32_t)((kb + a_kadd) ^ a_swrow);
        ldmx4(ahr, a_base + OFF_AHI + a_off);
        ldmx4(alr, a_base + OFF_ALO + a_off);
#pragma unroll
        for (int ntp = 0; ntp < 4; ntp++) {
            const int n0 = ch * 64 + ntp * 16;
            const int b_row = n0 + b_rowoff;
            uint32_t b_off = (uint32_t)(b_row * 256 + ((kb + b_kadd) ^ ((b_row & 7) << 4)));
            uint32_t bh[4], bl[4];
            ldmx4(bh, smb + OFF_BHI + b_off);
            ldmx4(bl, smb + OFF_BLO + b_off);
            mma16816(acc[2 * ntp],     ahr, bh[0], bh[1]);
            mma16816(acc[2 * ntp + 1], ahr, bh[2], bh[3]);
            mma16816(acc[2 * ntp],     ahr, bl[0], bl[1]);
            mma16816(acc[2 * ntp + 1], ahr, bl[2], bl[3]);
            mma16816(acc[2 * ntp],     alr, bh[0], bh[1]);
            mma16816(acc[2 * ntp + 1], alr, bh[2], bh[3]);
        }
    }

    const int r_lo = row0 + m0 + (lane >> 2);
    const int cbase = ch * 64 + (lane & 3) * 2;
    if (r_lo < n) {
        float sc = scale ? scale[smap ? smap[r_lo] : r_lo] : 1.0f;
        __half* crow = C + (size_t)r_lo * D;
#pragma unroll
        for (int t = 0; t < 8; t++)
            *(__half2*)(crow + cbase + t * 8) = __floats2half2_rn(acc[t][0] * sc, acc[t][1] * sc);
    }
    const int r_hi = r_lo + 8;
    if (r_hi < n) {
        float sc = scale ? scale[smap ? smap[r_hi] : r_hi] : 1.0f;
        __half* crow = C + (size_t)r_hi * D;
#pragma unroll
        for (int t = 0; t < 8; t++)
            *(__half2*)(crow + cbase + t * 8) = __floats2half2_rn(acc[t][2] * sc, acc[t][3] * sc);
    }
}

// ================= final CSR gather (pre-scaled sources) -> fp32 out =================
__global__ void k_gather_s(const int* __restrict__ rp, const int* __restrict__ esrc,
                           const float* __restrict__ dinv, const __half* __restrict__ xw,
                           const float* __restrict__ bias, float* __restrict__ out, int n) {
    int row = blockIdx.x * (blockDim.x >> 5) + (threadIdx.x >> 5);
    if (row >= n) return;
    int lane = threadIdx.x & 31;
    float4 acc;
    {
        uint2 u = reinterpret_cast<const uint2*>(xw + (size_t)row * D)[lane];
        float2 f0 = __half22float2(*reinterpret_cast<__half2*>(&u.x));
        float2 f1 = __half22float2(*reinterpret_cast<__half2*>(&u.y));
        acc.x = f0.x; acc.y = f0.y; acc.z = f1.x; acc.w = f1.y;
    }
    int s0 = rp[row], s1 = rp[row + 1];
    for (int base = s0; base < s1; base += 32) {
        int cnt = min(32, s1 - base);
        int sid = 0;
        if (lane < cnt) sid = esrc[base + lane];
        for (int j = 0; j < cnt; j++) {
            int s = __shfl_sync(0xffffffffu, sid, j);
            uint2 u = reinterpret_cast<const uint2*>(xw + (size_t)s * D)[lane];
            float2 f0 = __half22float2(*reinterpret_cast<__half2*>(&u.x));
            float2 f1 = __half22float2(*reinterpret_cast<__half2*>(&u.y));
            acc.x += f0.x; acc.y += f0.y; acc.z += f1.x; acc.w += f1.y;
        }
    }
    float di = dinv[row];
    float4 bb = reinterpret_cast<const float4*>(bias)[lane];
    acc.x = acc.x * di + bb.x; acc.y = acc.y * di + bb.y;
    acc.z = acc.z * di + bb.z; acc.w = acc.w * di + bb.w;
    acc.x = acc.x > 0.f ? acc.x : expm1f(acc.x);
    acc.y = acc.y > 0.f ? acc.y : expm1f(acc.y);
    acc.z = acc.z > 0.f ? acc.z : expm1f(acc.z);
    acc.w = acc.w > 0.f ? acc.w : expm1f(acc.w);
    reinterpret_cast<float4*>(out)[(size_t)row * 32 + lane] = acc;
}

extern "C" void kernel_launch(void* const* d_in, const int* in_sizes, int n_in,
                              void* d_out, int out_size) {
    const int*   ei     = (const int*)d_in[1];
    const float* px     = (const float*)d_in[2];
    const int*   pei    = (const int*)d_in[3];
    const int*   unpool = (const int*)d_in[4];
    const float* b0 = (const float*)d_in[6];
    const float* b1 = (const float*)d_in[8];
    const float* b2 = (const float*)d_in[10];
    const float* W0 = (const float*)d_in[5];
    const float* W1 = (const float*)d_in[7];
    const float* W2 = (const float*)d_in[9];

    const int nf = in_sizes[0] / D;
    const int Ef = in_sizes[1] / 2;
    const int np = in_sizes[2] / D;
    const int Ep = in_sizes[3] / 2;
    float* out = (float*)d_out;

    __half *h1, *h2;
    float *dinvf, *dinvp;
    int *cntf, *rpf, *curf, *esrcf, *cntp, *rpp, *curp, *esrcp, *bsf, *bsp, *inv;
    unsigned char* wimg;
    cudaGetSymbolAddress((void**)&h1,    g_h1);
    cudaGetSymbolAddress((void**)&h2,    g_h2);
    cudaGetSymbolAddress((void**)&cntf,  g_cntf);
    cudaGetSymbolAddress((void**)&rpf,   g_rpf);
    cudaGetSymbolAddress((void**)&curf,  g_curf);
    cudaGetSymbolAddress((void**)&esrcf, g_esrcf);
    cudaGetSymbolAddress((void**)&dinvf, g_dinvf);
    cudaGetSymbolAddress((void**)&cntp,  g_cntp);
    cudaGetSymbolAddress((void**)&rpp,   g_rpp);
    cudaGetSymbolAddress((void**)&curp,  g_curp);
    cudaGetSymbolAddress((void**)&esrcp, g_esrcp);
    cudaGetSymbolAddress((void**)&dinvp, g_dinvp);
    cudaGetSymbolAddress((void**)&inv,   g_inv);
    cudaGetSymbolAddress((void**)&bsf,   g_bsf);
    cudaGetSymbolAddress((void**)&bsp,   g_bsp);
    cudaGetSymbolAddress((void**)&wimg,  g_wimg);

    const int GEMM_SMEM = 96 * 1024;
    cudaFuncSetAttribute(k_gemm_mma, cudaFuncAttributeMaxDynamicSharedMemorySize, GEMM_SMEM);
    cudaFuncSetAttribute(k_gather_gemm, cudaFuncAttributeMaxDynamicSharedMemorySize, GEMM_SMEM);

    const unsigned char* img0h = wimg;
    const unsigned char* img0l = wimg + 32768;
    const unsigned char* img1h = wimg + 2 * 32768;
    const unsigned char* img1l = wimg + 3 * 32768;
    const unsigned char* img2h = wimg + 4 * 32768;
    const unsigned char* img2l = wimg + 5 * 32768;

    const int nbf = cdiv(nf, 1024), nbp = cdiv(np, 1024);

    static cudaStream_t s1 = nullptr, s2 = nullptr;
    static cudaEvent_t ev_fork = nullptr, ev_g0 = nullptr, ev_csr = nullptr;
    if (!s1) {
        cudaStreamCreateWithFlags(&s1, cudaStreamNonBlocking);
        cudaStreamCreateWithFlags(&s2, cudaStreamNonBlocking);
        cudaEventCreateWithFlags(&ev_fork, cudaEventDisableTiming);
        cudaEventCreateWithFlags(&ev_g0, cudaEventDisableTiming);
        cudaEventCreateWithFlags(&ev_csr, cudaEventDisableTiming);
    }

    // ---- prologue (main stream) ----
    k_zero_prep<<<cdiv(nf, 256), 256>>>(cntf, cntp, inv, nf, np, W0, W1, W2);
    cudaEventRecord(ev_fork, 0);

    // s1: inv index + GEMM0 (px @ W0 -> h1, half, unscaled; np rows)
    cudaStreamWaitEvent(s1, ev_fork, 0);
    k_inv<<<cdiv(np, 256), 256, 0, s1>>>(unpool, inv, np);
    k_gemm_mma<<<cdiv(np, 64), 256, GEMM_SMEM, s1>>>(px, img0h, img0l, h1, np);
    cudaEventRecord(ev_g0, s1);

    // s2: full-graph CSR (dinvf needed by fused0 epilogue onward)
    cudaStreamWaitEvent(s2, ev_fork, 0);
    k_hist<<<cdiv(Ef, 256), 256, 0, s2>>>(ei + Ef, Ef, cntf);
    k_bsum<<<nbf, 256, 0, s2>>>(cntf, nf, bsf);
    k_write<<<nbf, 256, 0, s2>>>(cntf, nf, bsf, nbf, rpf, curf, dinvf);
    k_place<<<cdiv(Ef, 256), 256, 0, s2>>>(ei, ei + Ef, Ef, curf, esrcf);
    cudaEventRecord(ev_csr, s2);

    // main: pooled CSR (short)
    k_hist<<<cdiv(Ep, 256), 256>>>(pei + Ep, Ep, cntp);
    k_bsum<<<nbp, 256>>>(cntp, np, bsp);
    k_write<<<nbp, 256>>>(cntp, np, bsp, nbp, rpp, curp, dinvp);
    k_place<<<cdiv(Ep, 256), 256>>>(pei, pei + Ep, Ep, curp, esrcp);

    // fused0: gather0 (pooled, per-edge dinvp, +b0, ELU) + GEMM1 (scale dinvf[unpool[r]]) -> h2
    cudaStreamWaitEvent(0, ev_g0, 0);
    cudaStreamWaitEvent(0, ev_csr, 0);
    k_gather_gemm<<<cdiv(np, 64), 256, GEMM_SMEM>>>(
        rpp, esrcp, dinvp, h1, b0, nullptr, 1,
        img1h, img1l, h2, np, dinvf, unpool);

    // fused1: gather1 (full, prescaled h2, inv, +b1, ELU) + GEMM2 (scale dinvf[row]) -> h1
    k_gather_gemm<<<cdiv(nf, 64), 256, GEMM_SMEM>>>(
        rpf, esrcf, dinvf, h2, b1, inv, 0,
        img2h, img2l, h1, nf, dinvf, nullptr);

    // final gather -> out
    k_gather_s<<<cdiv(nf, 8), 256>>>(rpf, esrcf, dinvf, h1, b2, out, nf);
}

// round 15
// speedup vs baseline: 1.0519x; 1.0519x over previous
#include <cuda_runtime.h>
#include <cuda_bf16.h>
#include <cuda_fp16.h>
#include <math.h>
#include <stdint.h>

#define D 128
#define NF_MAX 50000
#define NP_MAX 12500
#define EF_MAX 600000

// ---------------- scratch (static device globals) ----------------
__device__ __half g_h1[(size_t)NF_MAX * D];
__device__ __half g_h2[(size_t)NP_MAX * D];
__device__ float  g_buf2[(size_t)NF_MAX * D];
__device__ int    g_cntf[NF_MAX];
__device__ int    g_rpf[NF_MAX + 1];
__device__ int    g_curf[NF_MAX];
__device__ int    g_esrcf[EF_MAX];
__device__ float  g_dinvf[NF_MAX];
__device__ int    g_cntp[NP_MAX];
__device__ int    g_rpp[NP_MAX + 1];
__device__ int    g_curp[NP_MAX];
__device__ int    g_esrcp[EF_MAX / 4];
__device__ float  g_dinvp[NP_MAX];
__device__ int    g_inv[NF_MAX];
__device__ int    g_bsf[64];
__device__ int    g_bsp[64];
__device__ unsigned char g_wimg[3][2][32768];

static inline int cdiv(int a, int b) { return (a + b - 1) / b; }

__host__ __device__ __forceinline__ uint32_t swz(int row, int kbyte) {
    return (uint32_t)(row * 256 + (kbyte ^ ((row & 7) << 4)));
}

__device__ __forceinline__ uint32_t smem_u32(const void* p) {
    uint32_t a;
    asm("{ .reg .u64 t; cvta.to.shared.u64 t, %1; cvt.u32.u64 %0, t; }" : "=r"(a) : "l"(p));
    return a;
}
__device__ __forceinline__ void ldmx4(uint32_t* r, uint32_t addr) {
    asm volatile("ldmatrix.sync.aligned.m8n8.x4.shared.b16 {%0,%1,%2,%3}, [%4];"
                 : "=r"(r[0]), "=r"(r[1]), "=r"(r[2]), "=r"(r[3]) : "r"(addr));
}
__device__ __forceinline__ void mma16816(float* c, const uint32_t* a, uint32_t b0, uint32_t b1) {
    asm volatile("mma.sync.aligned.m16n8k16.row.col.f32.bf16.bf16.f32 "
                 "{%0,%1,%2,%3}, {%4,%5,%6,%7}, {%8,%9}, {%0,%1,%2,%3};"
                 : "+f"(c[0]), "+f"(c[1]), "+f"(c[2]), "+f"(c[3])
                 : "r"(a[0]), "r"(a[1]), "r"(a[2]), "r"(a[3]), "r"(b0), "r"(b1));
}
__device__ __forceinline__ void h2acc(float4& acc, uint2 u, float w) {
    float2 f0 = __half22float2(*reinterpret_cast<__half2*>(&u.x));
    float2 f1 = __half22float2(*reinterpret_cast<__half2*>(&u.y));
    acc.x += f0.x * w; acc.y += f0.y * w; acc.z += f1.x * w; acc.w += f1.y * w;
}

// ================= fused zero + W-prep =================
__global__ void k_zero_prep(int* cntf, int* cntp, int* inv, int nf, int np,
                            const float* __restrict__ W0, const float* __restrict__ W1,
                            const float* __restrict__ W2) {
    int i = blockIdx.x * blockDim.x + threadIdx.x;
    if (i < nf) { cntf[i] = 0; inv[i] = -1; }
    if (i < np) cntp[i] = 0;
    if (i < 3 * 128 * 128) {
        int w = i >> 14, rem = i & 16383;
        int k = rem >> 7, n = rem & 127;
        const float* W = (w == 0) ? W0 : (w == 1) ? W1 : W2;
        float v = W[k * 128 + n];
        __nv_bfloat16 hb = __float2bfloat16(v);
        float r = v - __bfloat162float(hb);
        __nv_bfloat16 lb = __float2bfloat16(r);
        uint32_t sw = swz(n, k * 2);
        *(unsigned short*)(&g_wimg[w][0][sw]) = __bfloat16_as_ushort(hb);
        *(unsigned short*)(&g_wimg[w][1][sw]) = __bfloat16_as_ushort(lb);
    }
}

__global__ void k_inv(const int* __restrict__ unpool, int* __restrict__ inv, int np) {
    int r = blockIdx.x * blockDim.x + threadIdx.x;
    if (r < np) inv[unpool[r]] = r;
}

// ================= single-graph CSR kernels =================
__global__ void k_hist(const int* __restrict__ dst, int E, int* __restrict__ cnt) {
    int e = blockIdx.x * blockDim.x + threadIdx.x;
    if (e < E) atomicAdd(&cnt[dst[e]], 1);
}

__global__ void k_bsum(const int* __restrict__ cnt, int n, int* __restrict__ bs) {
    int b = blockIdx.x;
    int tid = threadIdx.x, lane = tid & 31, warp = tid >> 5;
    int i0 = b * 1024 + tid * 4;
    int s = 0;
#pragma unroll
    for (int k = 0; k < 4; k++) if (i0 + k < n) s += cnt[i0 + k];
#pragma unroll
    for (int off = 16; off > 0; off >>= 1) s += __shfl_down_sync(0xffffffffu, s, off);
    __shared__ int ws[8];
    if (lane == 0) ws[warp] = s;
    __syncthreads();
    if (tid == 0) {
        int t = 0;
#pragma unroll
        for (int w = 0; w < 8; w++) t += ws[w];
        bs[b] = t;
    }
}

__global__ void k_write(const int* __restrict__ cnt, int n, const int* __restrict__ bs, int nb,
                        int* __restrict__ rp, int* __restrict__ cur, float* __restrict__ dinv) {
    __shared__ int sbs[64];
    __shared__ int ws[8];
    int b = blockIdx.x;
    int tid = threadIdx.x, lane = tid & 31, warp = tid >> 5;
    if (tid < 64) sbs[tid] = (tid < nb) ? bs[tid] : 0;
    __syncthreads();
#pragma unroll
    for (int off = 1; off < 64; off <<= 1) {
        int add = (tid >= off && tid < 64) ? sbs[tid - off] : 0;
        __syncthreads();
        if (tid < 64) sbs[tid] += add;
        __syncthreads();
    }
    int i0 = b * 1024 + tid * 4;
    int v[4];
#pragma unroll
    for (int k = 0; k < 4; k++) v[k] = (i0 + k < n) ? cnt[i0 + k] : 0;
    int s = v[0] + v[1] + v[2] + v[3];
    int inc = s;
#pragma unroll
    for (int off = 1; off < 32; off <<= 1) {
        int u = __shfl_up_sync(0xffffffffu, inc, off);
        if (lane >= off) inc += u;
    }
    if (lane == 31) ws[warp] = inc;
    __syncthreads();
    int woff = 0;
#pragma unroll
    for (int w = 0; w < 8; w++) if (w < warp) woff += ws[w];
    int blockoff = b ? sbs[b - 1] : 0;
    int pre = blockoff + woff + inc - s;
#pragma unroll
    for (int k = 0; k < 4; k++) {
        int i = i0 + k;
        if (i < n) {
            rp[i] = pre; cur[i] = pre;
            dinv[i] = rsqrtf((float)v[k] + 1.0f);
            pre += v[k];
        }
    }
    if (b == 0 && tid == 0) rp[n] = sbs[63];
}

__global__ void k_place(const int* __restrict__ src, const int* __restrict__ dst, int E,
                        int* __restrict__ cur, int* __restrict__ esrc) {
    int e = blockIdx.x * blockDim.x + threadIdx.x;
    if (e < E) {
        int p = atomicAdd(&cur[dst[e]], 1);
        esrc[p] = src[e];
    }
}

// ================= tensor-core GEMM, M=64 tiles =================
__global__ void __launch_bounds__(256, 1) k_gemm_mma(
    const float* __restrict__ A, const unsigned char* __restrict__ Whi,
    const unsigned char* __restrict__ Wlo, __half* __restrict__ C, int n,
    const float* __restrict__ scale, const int* __restrict__ smap) {
    extern __shared__ unsigned char sm[];
    const int OFF_AHI = 0, OFF_ALO = 16384, OFF_BHI = 32768, OFF_BLO = 65536;
    const uint32_t smb = smem_u32(sm);
    const int tid = threadIdx.x, wid = tid >> 5, lane = tid & 31;
    const int row0 = blockIdx.x * 64;

    for (int i = tid; i < 2048; i += 256) {
        ((float4*)(sm + OFF_BHI))[i] = ((const float4*)Whi)[i];
        ((float4*)(sm + OFF_BLO))[i] = ((const float4*)Wlo)[i];
    }
    {
        int row = tid >> 2, quarter = tid & 3;
        int gr = row0 + row;
        const float4* Arow = (const float4*)(A + (size_t)gr * D) + quarter * 8;
        unsigned char* ahi = sm + OFF_AHI;
        unsigned char* alo = sm + OFF_ALO;
#pragma unroll
        for (int q = 0; q < 8; q++) {
            float4 v = (gr < n) ? Arow[q] : make_float4(0.f, 0.f, 0.f, 0.f);
            float f[4] = {v.x, v.y, v.z, v.w};
#pragma unroll
            for (int p = 0; p < 2; p++) {
                float a0 = f[p * 2], a1 = f[p * 2 + 1];
                __nv_bfloat16 h0 = __float2bfloat16(a0), h1 = __float2bfloat16(a1);
                float r0 = a0 - __bfloat162float(h0);
                float r1 = a1 - __bfloat162float(h1);
                __nv_bfloat16 l0 = __float2bfloat16(r0), l1 = __float2bfloat16(r1);
                uint32_t uhi = (uint32_t)__bfloat16_as_ushort(h0) | ((uint32_t)__bfloat16_as_ushort(h1) << 16);
                uint32_t ulo = (uint32_t)__bfloat16_as_ushort(l0) | ((uint32_t)__bfloat16_as_ushort(l1) << 16);
                int k = quarter * 32 + q * 4 + p * 2;
                uint32_t sw = swz(row, k * 2);
                *(uint32_t*)(ahi + sw) = uhi;
                *(uint32_t*)(alo + sw) = ulo;
            }
        }
    }
    __syncthreads();

    const int rg = wid & 3, ch = wid >> 2;
    const int m0 = rg * 16;
    float acc[8][4];
#pragma unroll
    for (int t = 0; t < 8; t++)
#pragma unroll
        for (int q = 0; q < 4; q++) acc[t][q] = 0.f;

    const int a_row = m0 + (lane & 15);
    const uint32_t a_base = smb + (uint32_t)(a_row * 256);
    const int a_swrow = (a_row & 7) << 4;
    const int a_kadd = (lane >> 4) * 16;
    const int b_rowoff = (lane & 7) + (lane >> 4) * 8;
    const int b_kadd = ((lane >> 3) & 1) * 16;

#pragma unroll 2
    for (int k0 = 0; k0 < 8; k0++) {
        const int kb = k0 * 32;
        uint32_t ahi[4], alo[4];
        uint32_t a_off = (uint32_t)((kb + a_kadd) ^ a_swrow);
        ldmx4(ahi, a_base + OFF_AHI + a_off);
        ldmx4(alo, a_base + OFF_ALO + a_off);
#pragma unroll
        for (int ntp = 0; ntp < 4; ntp++) {
            const int n0 = ch * 64 + ntp * 16;
            const int b_row = n0 + b_rowoff;
            uint32_t b_off = (uint32_t)(b_row * 256 + ((kb + b_kadd) ^ ((b_row & 7) << 4)));
            uint32_t bh[4], bl[4];
            ldmx4(bh, smb + OFF_BHI + b_off);
            ldmx4(bl, smb + OFF_BLO + b_off);
            mma16816(acc[2 * ntp],     ahi, bh[0], bh[1]);
            mma16816(acc[2 * ntp + 1], ahi, bh[2], bh[3]);
            mma16816(acc[2 * ntp],     ahi, bl[0], bl[1]);
            mma16816(acc[2 * ntp + 1], ahi, bl[2], bl[3]);
            mma16816(acc[2 * ntp],     alo, bh[0], bh[1]);
            mma16816(acc[2 * ntp + 1], alo, bh[2], bh[3]);
        }
    }

    const int r_lo = row0 + m0 + (lane >> 2);
    const int cbase = ch * 64 + (lane & 3) * 2;
    if (r_lo < n) {
        float sc = scale ? scale[smap ? smap[r_lo] : r_lo] : 1.0f;
        __half* crow = C + (size_t)r_lo * D;
#pragma unroll
        for (int t = 0; t < 8; t++)
            *(__half2*)(crow + cbase + t * 8) = __floats2half2_rn(acc[t][0] * sc, acc[t][1] * sc);
    }
    const int r_hi = r_lo + 8;
    if (r_hi < n) {
        float sc = scale ? scale[smap ? smap[r_hi] : r_hi] : 1.0f;
        __half* crow = C + (size_t)r_hi * D;
#pragma unroll
        for (int t = 0; t < 8; t++)
            *(__half2*)(crow + cbase + t * 8) = __floats2half2_rn(acc[t][2] * sc, acc[t][3] * sc);
    }
}

// ================= CSR gather, per-edge dinv, TWO rows per warp (conv0) =================
__global__ void k_gather2(const int* __restrict__ rp, const int* __restrict__ esrc,
                          const float* __restrict__ dinv, const __half* __restrict__ xw,
                          const float* __restrict__ bias, float* __restrict__ out, int n) {
    int w = blockIdx.x * (blockDim.x >> 5) + (threadIdx.x >> 5);
    int r0 = w * 2, r1 = r0 + 1;
    if (r0 >= n) return;
    bool has1 = r1 < n;
    int lane = threadIdx.x & 31;
    float di0 = dinv[r0];
    float di1 = has1 ? dinv[r1] : 0.f;
    float4 acc0, acc1 = make_float4(0.f, 0.f, 0.f, 0.f);
    {
        uint2 u = reinterpret_cast<const uint2*>(xw + (size_t)r0 * D)[lane];
        acc0 = make_float4(0.f, 0.f, 0.f, 0.f);
        h2acc(acc0, u, di0 * di0);
        if (has1) {
            uint2 v = reinterpret_cast<const uint2*>(xw + (size_t)r1 * D)[lane];
            h2acc(acc1, v, di1 * di1);
        }
    }
    int a0 = rp[r0], a1 = rp[r0 + 1];
    int b1 = has1 ? rp[r1 + 1] : a1;
    int baseA = a0, baseB = a1;  // row1 edges start at rp[r1] == a1
    while (baseA < a1 || baseB < b1) {
        int cntA = min(32, max(0, a1 - baseA));
        int cntB = min(32, max(0, b1 - baseB));
        int sidA = -1, sidB = -1;
        float dvA = 0.f, dvB = 0.f;
        if (lane < cntA) { int s = esrc[baseA + lane]; dvA = dinv[s]; sidA = s; }
        if (lane < cntB) { int s = esrc[baseB + lane]; dvB = dinv[s]; sidB = s; }
        int m = max(cntA, cntB);
        for (int j = 0; j < m; j++) {
            int sA = __shfl_sync(0xffffffffu, sidA, j);
            int sB = __shfl_sync(0xffffffffu, sidB, j);
            float wA = __shfl_sync(0xffffffffu, dvA, j) * di0;
            float wB = __shfl_sync(0xffffffffu, dvB, j) * di1;
            uint2 uA, uB;
            bool vA = (j < cntA), vB = (j < cntB);
            if (vA) uA = reinterpret_cast<const uint2*>(xw + (size_t)sA * D)[lane];
            if (vB) uB = reinterpret_cast<const uint2*>(xw + (size_t)sB * D)[lane];
            if (vA) h2acc(acc0, uA, wA);
            if (vB) h2acc(acc1, uB, wB);
        }
        baseA += 32; baseB += 32;
    }
    float4 bb = reinterpret_cast<const float4*>(bias)[lane];
    acc0.x += bb.x; acc0.y += bb.y; acc0.z += bb.z; acc0.w += bb.w;
    acc0.x = acc0.x > 0.f ? acc0.x : expm1f(acc0.x);
    acc0.y = acc0.y > 0.f ? acc0.y : expm1f(acc0.y);
    acc0.z = acc0.z > 0.f ? acc0.z : expm1f(acc0.z);
    acc0.w = acc0.w > 0.f ? acc0.w : expm1f(acc0.w);
    reinterpret_cast<float4*>(out)[(size_t)r0 * 32 + lane] = acc0;
    if (has1) {
        acc1.x += bb.x; acc1.y += bb.y; acc1.z += bb.z; acc1.w += bb.w;
        acc1.x = acc1.x > 0.f ? acc1.x : expm1f(acc1.x);
        acc1.y = acc1.y > 0.f ? acc1.y : expm1f(acc1.y);
        acc1.z = acc1.z > 0.f ? acc1.z : expm1f(acc1.z);
        acc1.w = acc1.w > 0.f ? acc1.w : expm1f(acc1.w);
        reinterpret_cast<float4*>(out)[(size_t)r1 * 32 + lane] = acc1;
    }
}

// ========== CSR gather, pre-scaled sources, TWO rows per warp, optional inv ==========
// writeHalf: out interpreted as fp32 buffer always (gather1 -> buf2; gather2 -> out)
__global__ void k_gather_s2(const int* __restrict__ rp, const int* __restrict__ esrc,
                            const float* __restrict__ dinv, const __half* __restrict__ xw,
                            const float* __restrict__ bias, const int* __restrict__ inv,
                            float* __restrict__ out, int n) {
    int w = blockIdx.x * (blockDim.x >> 5) + (threadIdx.x >> 5);
    int r0 = w * 2, r1 = r0 + 1;
    if (r0 >= n) return;
    bool has1 = r1 < n;
    int lane = threadIdx.x & 31;
    float4 acc0 = make_float4(0.f, 0.f, 0.f, 0.f);
    float4 acc1 = make_float4(0.f, 0.f, 0.f, 0.f);
    {
        int s0 = inv ? inv[r0] : r0;
        if (s0 >= 0) {
            uint2 u = reinterpret_cast<const uint2*>(xw + (size_t)s0 * D)[lane];
            h2acc(acc0, u, 1.0f);
        }
        if (has1) {
            int s1 = inv ? inv[r1] : r1;
            if (s1 >= 0) {
                uint2 v = reinterpret_cast<const uint2*>(xw + (size_t)s1 * D)[lane];
                h2acc(acc1, v, 1.0f);
            }
        }
    }
    int a0 = rp[r0], a1 = rp[r0 + 1];
    int b1 = has1 ? rp[r1 + 1] : a1;
    int baseA = a0, baseB = a1;
    while (baseA < a1 || baseB < b1) {
        int cntA = min(32, max(0, a1 - baseA));
        int cntB = min(32, max(0, b1 - baseB));
        int sidA = -1, sidB = -1;
        if (lane < cntA) { int s = esrc[baseA + lane]; sidA = inv ? inv[s] : s; }
        if (lane < cntB) { int s = esrc[baseB + lane]; sidB = inv ? inv[s] : s; }
        int m = max(cntA, cntB);
        for (int j = 0; j < m; j++) {
            int sA = __shfl_sync(0xffffffffu, sidA, j);
            int sB = __shfl_sync(0xffffffffu, sidB, j);
            uint2 uA, uB;
            bool vA = (j < cntA && sA >= 0), vB = (j < cntB && sB >= 0);
            if (vA) uA = reinterpret_cast<const uint2*>(xw + (size_t)sA * D)[lane];
            if (vB) uB = reinterpret_cast<const uint2*>(xw + (size_t)sB * D)[lane];
            if (vA) h2acc(acc0, uA, 1.0f);
            if (vB) h2acc(acc1, uB, 1.0f);
        }
        baseA += 32; baseB += 32;
    }
    float4 bb = reinterpret_cast<const float4*>(bias)[lane];
    float di0 = dinv[r0];
    acc0.x = acc0.x * di0 + bb.x; acc0.y = acc0.y * di0 + bb.y;
    acc0.z = acc0.z * di0 + bb.z; acc0.w = acc0.w * di0 + bb.w;
    acc0.x = acc0.x > 0.f ? acc0.x : expm1f(acc0.x);
    acc0.y = acc0.y > 0.f ? acc0.y : expm1f(acc0.y);
    acc0.z = acc0.z > 0.f ? acc0.z : expm1f(acc0.z);
    acc0.w = acc0.w > 0.f ? acc0.w : expm1f(acc0.w);
    reinterpret_cast<float4*>(out)[(size_t)r0 * 32 + lane] = acc0;
    if (has1) {
        float di1 = dinv[r1];
        acc1.x = acc1.x * di1 + bb.x; acc1.y = acc1.y * di1 + bb.y;
        acc1.z = acc1.z * di1 + bb.z; acc1.w = acc1.w * di1 + bb.w;
        acc1.x = acc1.x > 0.f ? acc1.x : expm1f(acc1.x);
        acc1.y = acc1.y > 0.f ? acc1.y : expm1f(acc1.y);
        acc1.z = acc1.z > 0.f ? acc1.z : expm1f(acc1.z);
        acc1.w = acc1.w > 0.f ? acc1.w : expm1f(acc1.w);
        reinterpret_cast<float4*>(out)[(size_t)r1 * 32 + lane] = acc1;
    }
}

extern "C" void kernel_launch(void* const* d_in, const int* in_sizes, int n_in,
                              void* d_out, int out_size) {
    const int*   ei     = (const int*)d_in[1];
    const float* px     = (const float*)d_in[2];
    const int*   pei    = (const int*)d_in[3];
    const int*   unpool = (const int*)d_in[4];
    const float* W0 = (const float*)d_in[5];
    const float* b0 = (const float*)d_in[6];
    const float* W1 = (const float*)d_in[7];
    const float* b1 = (const float*)d_in[8];
    const float* W2 = (const float*)d_in[9];
    const float* b2 = (const float*)d_in[10];

    const int nf = in_sizes[0] / D;
    const int Ef = in_sizes[1] / 2;
    const int np = in_sizes[2] / D;
    const int Ep = in_sizes[3] / 2;
    float* out = (float*)d_out;

    __half *h1, *h2;
    float *buf2, *dinvf, *dinvp;
    int *cntf, *rpf, *curf, *esrcf, *cntp, *rpp, *curp, *esrcp, *bsf, *bsp, *inv;
    unsigned char* wimg;
    cudaGetSymbolAddress((void**)&h1,    g_h1);
    cudaGetSymbolAddress((void**)&h2,    g_h2);
    cudaGetSymbolAddress((void**)&buf2,  g_buf2);
    cudaGetSymbolAddress((void**)&cntf,  g_cntf);
    cudaGetSymbolAddress((void**)&rpf,   g_rpf);
    cudaGetSymbolAddress((void**)&curf,  g_curf);
    cudaGetSymbolAddress((void**)&esrcf, g_esrcf);
    cudaGetSymbolAddress((void**)&dinvf, g_dinvf);
    cudaGetSymbolAddress((void**)&cntp,  g_cntp);
    cudaGetSymbolAddress((void**)&rpp,   g_rpp);
    cudaGetSymbolAddress((void**)&curp,  g_curp);
    cudaGetSymbolAddress((void**)&esrcp, g_esrcp);
    cudaGetSymbolAddress((void**)&dinvp, g_dinvp);
    cudaGetSymbolAddress((void**)&inv,   g_inv);
    cudaGetSymbolAddress((void**)&bsf,   g_bsf);
    cudaGetSymbolAddress((void**)&bsp,   g_bsp);
    cudaGetSymbolAddress((void**)&wimg,  g_wimg);

    const int GEMM_SMEM = 96 * 1024;
    cudaFuncSetAttribute(k_gemm_mma, cudaFuncAttributeMaxDynamicSharedMemorySize, GEMM_SMEM);

    const unsigned char* img0h = wimg;
    const unsigned char* img0l = wimg + 32768;
    const unsigned char* img1h = wimg + 2 * 32768;
    const unsigned char* img1l = wimg + 3 * 32768;
    const unsigned char* img2h = wimg + 4 * 32768;
    const unsigned char* img2l = wimg + 5 * 32768;

    const int nbf = cdiv(nf, 1024), nbp = cdiv(np, 1024);

    static cudaStream_t s1 = nullptr, s2 = nullptr;
    static cudaEvent_t ev_fork = nullptr, ev_g0 = nullptr, ev_csr = nullptr;
    if (!s1) {
        cudaStreamCreateWithFlags(&s1, cudaStreamNonBlocking);
        cudaStreamCreateWithFlags(&s2, cudaStreamNonBlocking);
        cudaEventCreateWithFlags(&ev_fork, cudaEventDisableTiming);
        cudaEventCreateWithFlags(&ev_g0, cudaEventDisableTiming);
        cudaEventCreateWithFlags(&ev_csr, cudaEventDisableTiming);
    }

    // ---- prologue (main stream) ----
    k_zero_prep<<<cdiv(nf, 256), 256>>>(cntf, cntp, inv, nf, np, W0, W1, W2);
    cudaEventRecord(ev_fork, 0);

    // s1: inv index + GEMM0 (px @ W0 -> h1, unscaled)
    cudaStreamWaitEvent(s1, ev_fork, 0);
    k_inv<<<cdiv(np, 256), 256, 0, s1>>>(unpool, inv, np);
    k_gemm_mma<<<cdiv(np, 64), 256, GEMM_SMEM, s1>>>(px, img0h, img0l, h1, np, nullptr, nullptr);
    cudaEventRecord(ev_g0, s1);

    // s2: full-graph CSR
    cudaStreamWaitEvent(s2, ev_fork, 0);
    k_hist<<<cdiv(Ef, 256), 256, 0, s2>>>(ei + Ef, Ef, cntf);
    k_bsum<<<nbf, 256, 0, s2>>>(cntf, nf, bsf);
    k_write<<<nbf, 256, 0, s2>>>(cntf, nf, bsf, nbf, rpf, curf, dinvf);
    k_place<<<cdiv(Ef, 256), 256, 0, s2>>>(ei, ei + Ef, Ef, curf, esrcf);
    cudaEventRecord(ev_csr, s2);

    // main: pooled CSR (short)
    k_hist<<<cdiv(Ep, 256), 256>>>(pei + Ep, Ep, cntp);
    k_bsum<<<nbp, 256>>>(cntp, np, bsp);
    k_write<<<nbp, 256>>>(cntp, np, bsp, nbp, rpp, curp, dinvp);
    k_place<<<cdiv(Ep, 256), 256>>>(pei, pei + Ep, Ep, curp, esrcp);

    // conv0 gather (per-edge dinv; 2 rows/warp; needs GEMM0)
    cudaStreamWaitEvent(0, ev_g0, 0);
    k_gather2<<<cdiv(np, 16), 256>>>(rpp, esrcp, dinvp, h1, b0, buf2, np);

    // conv1: compact GEMM with dinvf[unpool[r]] epilogue scale (needs full CSR)
    cudaStreamWaitEvent(0, ev_csr, 0);
    k_gemm_mma<<<cdiv(np, 64), 256, GEMM_SMEM>>>(buf2, img1h, img1l, h2, np, dinvf, unpool);
    k_gather_s2<<<cdiv(nf, 16), 256>>>(rpf, esrcf, dinvf, h2, b1, inv, buf2, nf);

    // conv2: full GEMM with dinvf[row] epilogue scale + pre-scaled gather -> out
    k_gemm_mma<<<cdiv(nf, 64), 256, GEMM_SMEM>>>(buf2, img2h, img2l, h1, nf, dinvf, nullptr);
    k_gather_s2<<<cdiv(nf, 16), 256>>>(rpf, esrcf, dinvf, h1, b2, nullptr, out, nf);
}

// round 16
// speedup vs baseline: 1.1635x; 1.1061x over previous
#include <cuda_runtime.h>
#include <cuda_bf16.h>
#include <cuda_fp16.h>
#include <math.h>
#include <stdint.h>

#define D 128
#define NF_MAX 50000
#define NP_MAX 12500
#define EF_MAX 600000

// ---------------- scratch (static device globals) ----------------
__device__ __half g_h1[(size_t)NF_MAX * D];   // GEMM0 out (np) / GEMM2 out (nf)
__device__ __half g_h2[(size_t)NP_MAX * D];   // GEMM1 out (compact np)
__device__ float  g_buf2[(size_t)NF_MAX * D]; // gather outputs (fp32 GEMM inputs)
__device__ int    g_cntf[NF_MAX];
__device__ int    g_rpf[NF_MAX + 1];
__device__ int    g_curf[NF_MAX];
__device__ int    g_esrcf[EF_MAX];
__device__ float  g_dinvf[NF_MAX];
__device__ int    g_cntp[NP_MAX];
__device__ int    g_rpp[NP_MAX + 1];
__device__ int    g_curp[NP_MAX];
__device__ int    g_esrcp[EF_MAX / 4];
__device__ float  g_dinvp[NP_MAX];
__device__ int    g_inv[NF_MAX];
__device__ int    g_bsf[64];
__device__ int    g_bsp[64];
__device__ unsigned char g_wimg[3][2][32768];

static inline int cdiv(int a, int b) { return (a + b - 1) / b; }

__host__ __device__ __forceinline__ uint32_t swz(int row, int kbyte) {
    return (uint32_t)(row * 256 + (kbyte ^ ((row & 7) << 4)));
}

__device__ __forceinline__ uint32_t smem_u32(const void* p) {
    uint32_t a;
    asm("{ .reg .u64 t; cvta.to.shared.u64 t, %1; cvt.u32.u64 %0, t; }" : "=r"(a) : "l"(p));
    return a;
}
__device__ __forceinline__ void ldmx4(uint32_t* r, uint32_t addr) {
    asm volatile("ldmatrix.sync.aligned.m8n8.x4.shared.b16 {%0,%1,%2,%3}, [%4];"
                 : "=r"(r[0]), "=r"(r[1]), "=r"(r[2]), "=r"(r[3]) : "r"(addr));
}
__device__ __forceinline__ void mma16816(float* c, const uint32_t* a, uint32_t b0, uint32_t b1) {
    asm volatile("mma.sync.aligned.m16n8k16.row.col.f32.bf16.bf16.f32 "
                 "{%0,%1,%2,%3}, {%4,%5,%6,%7}, {%8,%9}, {%0,%1,%2,%3};"
                 : "+f"(c[0]), "+f"(c[1]), "+f"(c[2]), "+f"(c[3])
                 : "r"(a[0]), "r"(a[1]), "r"(a[2]), "r"(a[3]), "r"(b0), "r"(b1));
}

// ================= fused zero + W-prep =================
__global__ void k_zero_prep(int* cntf, int* cntp, int* inv, int nf, int np,
                            const float* __restrict__ W0, const float* __restrict__ W1,
                            const float* __restrict__ W2) {
    int i = blockIdx.x * blockDim.x + threadIdx.x;
    if (i < nf) { cntf[i] = 0; inv[i] = -1; }
    if (i < np) cntp[i] = 0;
    if (i < 3 * 128 * 128) {
        int w = i >> 14, rem = i & 16383;
        int k = rem >> 7, n = rem & 127;
        const float* W = (w == 0) ? W0 : (w == 1) ? W1 : W2;
        float v = W[k * 128 + n];
        __nv_bfloat16 hb = __float2bfloat16(v);
        float r = v - __bfloat162float(hb);
        __nv_bfloat16 lb = __float2bfloat16(r);
        uint32_t sw = swz(n, k * 2);
        *(unsigned short*)(&g_wimg[w][0][sw]) = __bfloat16_as_ushort(hb);
        *(unsigned short*)(&g_wimg[w][1][sw]) = __bfloat16_as_ushort(lb);
    }
}

__global__ void k_inv(const int* __restrict__ unpool, int* __restrict__ inv, int np) {
    int r = blockIdx.x * blockDim.x + threadIdx.x;
    if (r < np) inv[unpool[r]] = r;
}

// ================= single-graph CSR kernels =================
__global__ void k_hist(const int* __restrict__ dst, int E, int* __restrict__ cnt) {
    int e = blockIdx.x * blockDim.x + threadIdx.x;
    if (e < E) atomicAdd(&cnt[dst[e]], 1);
}

__global__ void k_bsum(const int* __restrict__ cnt, int n, int* __restrict__ bs) {
    int b = blockIdx.x;
    int tid = threadIdx.x, lane = tid & 31, warp = tid >> 5;
    int i0 = b * 1024 + tid * 4;
    int s = 0;
#pragma unroll
    for (int k = 0; k < 4; k++) if (i0 + k < n) s += cnt[i0 + k];
#pragma unroll
    for (int off = 16; off > 0; off >>= 1) s += __shfl_down_sync(0xffffffffu, s, off);
    __shared__ int ws[8];
    if (lane == 0) ws[warp] = s;
    __syncthreads();
    if (tid == 0) {
        int t = 0;
#pragma unroll
        for (int w = 0; w < 8; w++) t += ws[w];
        bs[b] = t;
    }
}

// write with inline scan of block sums
__global__ void k_write(const int* __restrict__ cnt, int n, const int* __restrict__ bs, int nb,
                        int* __restrict__ rp, int* __restrict__ cur, float* __restrict__ dinv) {
    __shared__ int sbs[64];
    __shared__ int ws[8];
    int b = blockIdx.x;
    int tid = threadIdx.x, lane = tid & 31, warp = tid >> 5;
    if (tid < 64) sbs[tid] = (tid < nb) ? bs[tid] : 0;
    __syncthreads();
#pragma unroll
    for (int off = 1; off < 64; off <<= 1) {
        int add = (tid >= off && tid < 64) ? sbs[tid - off] : 0;
        __syncthreads();
        if (tid < 64) sbs[tid] += add;
        __syncthreads();
    }
    int i0 = b * 1024 + tid * 4;
    int v[4];
#pragma unroll
    for (int k = 0; k < 4; k++) v[k] = (i0 + k < n) ? cnt[i0 + k] : 0;
    int s = v[0] + v[1] + v[2] + v[3];
    int inc = s;
#pragma unroll
    for (int off = 1; off < 32; off <<= 1) {
        int u = __shfl_up_sync(0xffffffffu, inc, off);
        if (lane >= off) inc += u;
    }
    if (lane == 31) ws[warp] = inc;
    __syncthreads();
    int woff = 0;
#pragma unroll
    for (int w = 0; w < 8; w++) if (w < warp) woff += ws[w];
    int blockoff = b ? sbs[b - 1] : 0;
    int pre = blockoff + woff + inc - s;
#pragma unroll
    for (int k = 0; k < 4; k++) {
        int i = i0 + k;
        if (i < n) {
            rp[i] = pre; cur[i] = pre;
            dinv[i] = rsqrtf((float)v[k] + 1.0f);
            pre += v[k];
        }
    }
    if (b == 0 && tid == 0) rp[n] = sbs[63];
}

__global__ void k_place(const int* __restrict__ src, const int* __restrict__ dst, int E,
                        int* __restrict__ cur, int* __restrict__ esrc) {
    int e = blockIdx.x * blockDim.x + threadIdx.x;
    if (e < E) {
        int p = atomicAdd(&cur[dst[e]], 1);
        esrc[p] = src[e];
    }
}

// ================= tensor-core GEMM, M=64 tiles (96KB smem -> 2 blocks/SM) =================
__global__ void __launch_bounds__(256, 1) k_gemm_mma(
    const float* __restrict__ A, const unsigned char* __restrict__ Whi,
    const unsigned char* __restrict__ Wlo, __half* __restrict__ C, int n,
    const float* __restrict__ scale, const int* __restrict__ smap) {
    extern __shared__ unsigned char sm[];
    const int OFF_AHI = 0, OFF_ALO = 16384, OFF_BHI = 32768, OFF_BLO = 65536;
    const uint32_t smb = smem_u32(sm);
    const int tid = threadIdx.x, wid = tid >> 5, lane = tid & 31;
    const int row0 = blockIdx.x * 64;

    for (int i = tid; i < 2048; i += 256) {
        ((float4*)(sm + OFF_BHI))[i] = ((const float4*)Whi)[i];
        ((float4*)(sm + OFF_BLO))[i] = ((const float4*)Wlo)[i];
    }
    {
        int row = tid >> 2, quarter = tid & 3;
        int gr = row0 + row;
        const float4* Arow = (const float4*)(A + (size_t)gr * D) + quarter * 8;
        unsigned char* ahi = sm + OFF_AHI;
        unsigned char* alo = sm + OFF_ALO;
#pragma unroll
        for (int q = 0; q < 8; q++) {
            float4 v = (gr < n) ? Arow[q] : make_float4(0.f, 0.f, 0.f, 0.f);
            float f[4] = {v.x, v.y, v.z, v.w};
#pragma unroll
            for (int p = 0; p < 2; p++) {
                float a0 = f[p * 2], a1 = f[p * 2 + 1];
                __nv_bfloat16 h0 = __float2bfloat16(a0), h1 = __float2bfloat16(a1);
                float r0 = a0 - __bfloat162float(h0);
                float r1 = a1 - __bfloat162float(h1);
                __nv_bfloat16 l0 = __float2bfloat16(r0), l1 = __float2bfloat16(r1);
                uint32_t uhi = (uint32_t)__bfloat16_as_ushort(h0) | ((uint32_t)__bfloat16_as_ushort(h1) << 16);
                uint32_t ulo = (uint32_t)__bfloat16_as_ushort(l0) | ((uint32_t)__bfloat16_as_ushort(l1) << 16);
                int k = quarter * 32 + q * 4 + p * 2;
                uint32_t sw = swz(row, k * 2);
                *(uint32_t*)(ahi + sw) = uhi;
                *(uint32_t*)(alo + sw) = ulo;
            }
        }
    }
    __syncthreads();

    const int rg = wid & 3, ch = wid >> 2;
    const int m0 = rg * 16;
    float acc[8][4];
#pragma unroll
    for (int t = 0; t < 8; t++)
#pragma unroll
        for (int q = 0; q < 4; q++) acc[t][q] = 0.f;

    const int a_row = m0 + (lane & 15);
    const uint32_t a_base = smb + (uint32_t)(a_row * 256);
    const int a_swrow = (a_row & 7) << 4;
    const int a_kadd = (lane >> 4) * 16;
    const int b_rowoff = (lane & 7) + (lane >> 4) * 8;
    const int b_kadd = ((lane >> 3) & 1) * 16;

#pragma unroll 2
    for (int k0 = 0; k0 < 8; k0++) {
        const int kb = k0 * 32;
        uint32_t ahi[4], alo[4];
        uint32_t a_off = (uint32_t)((kb + a_kadd) ^ a_swrow);
        ldmx4(ahi, a_base + OFF_AHI + a_off);
        ldmx4(alo, a_base + OFF_ALO + a_off);
#pragma unroll
        for (int ntp = 0; ntp < 4; ntp++) {
            const int n0 = ch * 64 + ntp * 16;
            const int b_row = n0 + b_rowoff;
            uint32_t b_off = (uint32_t)(b_row * 256 + ((kb + b_kadd) ^ ((b_row & 7) << 4)));
            uint32_t bh[4], bl[4];
            ldmx4(bh, smb + OFF_BHI + b_off);
            ldmx4(bl, smb + OFF_BLO + b_off);
            mma16816(acc[2 * ntp],     ahi, bh[0], bh[1]);
            mma16816(acc[2 * ntp + 1], ahi, bh[2], bh[3]);
            mma16816(acc[2 * ntp],     ahi, bl[0], bl[1]);
            mma16816(acc[2 * ntp + 1], ahi, bl[2], bl[3]);
            mma16816(acc[2 * ntp],     alo, bh[0], bh[1]);
            mma16816(acc[2 * ntp + 1], alo, bh[2], bh[3]);
        }
    }

    const int r_lo = row0 + m0 + (lane >> 2);
    const int cbase = ch * 64 + (lane & 3) * 2;
    if (r_lo < n) {
        float sc = scale ? scale[smap ? smap[r_lo] : r_lo] : 1.0f;
        __half* crow = C + (size_t)r_lo * D;
#pragma unroll
        for (int t = 0; t < 8; t++)
            *(__half2*)(crow + cbase + t * 8) = __floats2half2_rn(acc[t][0] * sc, acc[t][1] * sc);
    }
    const int r_hi = r_lo + 8;
    if (r_hi < n) {
        float sc = scale ? scale[smap ? smap[r_hi] : r_hi] : 1.0f;
        __half* crow = C + (size_t)r_hi * D;
#pragma unroll
        for (int t = 0; t < 8; t++)
            *(__half2*)(crow + cbase + t * 8) = __floats2half2_rn(acc[t][2] * sc, acc[t][3] * sc);
    }
}

// ================= CSR gather, per-edge dinv (conv0) =================
__global__ void k_gather(const int* __restrict__ rp, const int* __restrict__ esrc,
                         const float* __restrict__ dinv, const __half* __restrict__ xw,
                         const float* __restrict__ bias, const int* __restrict__ inv,
                         float* __restrict__ out, int n) {
    int row = blockIdx.x * (blockDim.x >> 5) + (threadIdx.x >> 5);
    if (row >= n) return;
    int lane = threadIdx.x & 31;
    float di = dinv[row];
    float4 acc = make_float4(0.f, 0.f, 0.f, 0.f);
    {
        int sr = inv ? inv[row] : row;
        if (sr >= 0) {
            uint2 u = reinterpret_cast<const uint2*>(xw + (size_t)sr * D)[lane];
            float2 f0 = __half22float2(*reinterpret_cast<__half2*>(&u.x));
            float2 f1 = __half22float2(*reinterpret_cast<__half2*>(&u.y));
            float w = di * di;
            acc.x = f0.x * w; acc.y = f0.y * w; acc.z = f1.x * w; acc.w = f1.y * w;
        }
    }
    int s0 = rp[row], s1 = rp[row + 1];
    for (int base = s0; base < s1; base += 32) {
        int cnt = min(32, s1 - base);
        int sid = -1; float dv = 0.f;
        if (lane < cnt) {
            int s = esrc[base + lane];
            dv = dinv[s];
            sid = inv ? inv[s] : s;
        }
        for (int j = 0; j < cnt; j++) {
            int s   = __shfl_sync(0xffffffffu, sid, j);
            float w = __shfl_sync(0xffffffffu, dv, j) * di;
            if (s < 0) continue;
            uint2 u = reinterpret_cast<const uint2*>(xw + (size_t)s * D)[lane];
            float2 f0 = __half22float2(*reinterpret_cast<__half2*>(&u.x));
            float2 f1 = __half22float2(*reinterpret_cast<__half2*>(&u.y));
            acc.x += f0.x * w; acc.y += f0.y * w; acc.z += f1.x * w; acc.w += f1.y * w;
        }
    }
    float4 bb = reinterpret_cast<const float4*>(bias)[lane];
    acc.x += bb.x; acc.y += bb.y; acc.z += bb.z; acc.w += bb.w;
    acc.x = acc.x > 0.f ? acc.x : expm1f(acc.x);
    acc.y = acc.y > 0.f ? acc.y : expm1f(acc.y);
    acc.z = acc.z > 0.f ? acc.z : expm1f(acc.z);
    acc.w = acc.w > 0.f ? acc.w : expm1f(acc.w);
    reinterpret_cast<float4*>(out)[(size_t)row * 32 + lane] = acc;
}

// ================= CSR gather, pre-scaled sources =================
__global__ void k_gather_s(const int* __restrict__ rp, const int* __restrict__ esrc,
                           const float* __restrict__ dinv, const __half* __restrict__ xw,
                           const float* __restrict__ bias, const int* __restrict__ inv,
                           float* __restrict__ out, int n) {
    int row = blockIdx.x * (blockDim.x >> 5) + (threadIdx.x >> 5);
    if (row >= n) return;
    int lane = threadIdx.x & 31;
    float4 acc = make_float4(0.f, 0.f, 0.f, 0.f);
    {
        int sr = inv ? inv[row] : row;
        if (sr >= 0) {
            uint2 u = reinterpret_cast<const uint2*>(xw + (size_t)sr * D)[lane];
            float2 f0 = __half22float2(*reinterpret_cast<__half2*>(&u.x));
            float2 f1 = __half22float2(*reinterpret_cast<__half2*>(&u.y));
            acc.x = f0.x; acc.y = f0.y; acc.z = f1.x; acc.w = f1.y;
        }
    }
    int s0 = rp[row], s1 = rp[row + 1];
    for (int base = s0; base < s1; base += 32) {
        int cnt = min(32, s1 - base);
        int sid = -1;
        if (lane < cnt) {
            int s = esrc[base + lane];
            sid = inv ? inv[s] : s;
        }
        for (int j = 0; j < cnt; j++) {
            int s = __shfl_sync(0xffffffffu, sid, j);
            if (s < 0) continue;
            uint2 u = reinterpret_cast<const uint2*>(xw + (size_t)s * D)[lane];
            float2 f0 = __half22float2(*reinterpret_cast<__half2*>(&u.x));
            float2 f1 = __half22float2(*reinterpret_cast<__half2*>(&u.y));
            acc.x += f0.x; acc.y += f0.y; acc.z += f1.x; acc.w += f1.y;
        }
    }
    float di = dinv[row];
    float4 bb = reinterpret_cast<const float4*>(bias)[lane];
    acc.x = acc.x * di + bb.x; acc.y = acc.y * di + bb.y;
    acc.z = acc.z * di + bb.z; acc.w = acc.w * di + bb.w;
    acc.x = acc.x > 0.f ? acc.x : expm1f(acc.x);
    acc.y = acc.y > 0.f ? acc.y : expm1f(acc.y);
    acc.z = acc.z > 0.f ? acc.z : expm1f(acc.z);
    acc.w = acc.w > 0.f ? acc.w : expm1f(acc.w);
    reinterpret_cast<float4*>(out)[(size_t)row * 32 + lane] = acc;
}

extern "C" void kernel_launch(void* const* d_in, const int* in_sizes, int n_in,
                              void* d_out, int out_size) {
    const int*   ei     = (const int*)d_in[1];
    const float* px     = (const float*)d_in[2];
    const int*   pei    = (const int*)d_in[3];
    const int*   unpool = (const int*)d_in[4];
    const float* W0 = (const float*)d_in[5];
    const float* b0 = (const float*)d_in[6];
    const float* W1 = (const float*)d_in[7];
    const float* b1 = (const float*)d_in[8];
    const float* W2 = (const float*)d_in[9];
    const float* b2 = (const float*)d_in[10];

    const int nf = in_sizes[0] / D;
    const int Ef = in_sizes[1] / 2;
    const int np = in_sizes[2] / D;
    const int Ep = in_sizes[3] / 2;
    float* out = (float*)d_out;

    __half *h1, *h2;
    float *buf2, *dinvf, *dinvp;
    int *cntf, *rpf, *curf, *esrcf, *cntp, *rpp, *curp, *esrcp, *bsf, *bsp, *inv;
    unsigned char* wimg;
    cudaGetSymbolAddress((void**)&h1,    g_h1);
    cudaGetSymbolAddress((void**)&h2,    g_h2);
    cudaGetSymbolAddress((void**)&buf2,  g_buf2);
    cudaGetSymbolAddress((void**)&cntf,  g_cntf);
    cudaGetSymbolAddress((void**)&rpf,   g_rpf);
    cudaGetSymbolAddress((void**)&curf,  g_curf);
    cudaGetSymbolAddress((void**)&esrcf, g_esrcf);
    cudaGetSymbolAddress((void**)&dinvf, g_dinvf);
    cudaGetSymbolAddress((void**)&cntp,  g_cntp);
    cudaGetSymbolAddress((void**)&rpp,   g_rpp);
    cudaGetSymbolAddress((void**)&curp,  g_curp);
    cudaGetSymbolAddress((void**)&esrcp, g_esrcp);
    cudaGetSymbolAddress((void**)&dinvp, g_dinvp);
    cudaGetSymbolAddress((void**)&inv,   g_inv);
    cudaGetSymbolAddress((void**)&bsf,   g_bsf);
    cudaGetSymbolAddress((void**)&bsp,   g_bsp);
    cudaGetSymbolAddress((void**)&wimg,  g_wimg);

    const int GEMM_SMEM = 96 * 1024;
    cudaFuncSetAttribute(k_gemm_mma, cudaFuncAttributeMaxDynamicSharedMemorySize, GEMM_SMEM);

    const unsigned char* img0h = wimg;
    const unsigned char* img0l = wimg + 32768;
    const unsigned char* img1h = wimg + 2 * 32768;
    const unsigned char* img1l = wimg + 3 * 32768;
    const unsigned char* img2h = wimg + 4 * 32768;
    const unsigned char* img2l = wimg + 5 * 32768;

    const int nbf = cdiv(nf, 1024), nbp = cdiv(np, 1024);

    static cudaStream_t s1 = nullptr, s2 = nullptr;
    static cudaEvent_t ev_fork = nullptr, ev_g0 = nullptr, ev_dinv = nullptr, ev_place = nullptr;
    if (!s1) {
        cudaStreamCreateWithFlags(&s1, cudaStreamNonBlocking);
        cudaStreamCreateWithFlags(&s2, cudaStreamNonBlocking);
        cudaEventCreateWithFlags(&ev_fork, cudaEventDisableTiming);
        cudaEventCreateWithFlags(&ev_g0, cudaEventDisableTiming);
        cudaEventCreateWithFlags(&ev_dinv, cudaEventDisableTiming);
        cudaEventCreateWithFlags(&ev_place, cudaEventDisableTiming);
    }

    // ---- prologue (main stream) ----
    k_zero_prep<<<cdiv(nf, 256), 256>>>(cntf, cntp, inv, nf, np, W0, W1, W2);
    cudaEventRecord(ev_fork, 0);

    // s1: inv index + GEMM0 (px @ W0 -> h1, unscaled)
    cudaStreamWaitEvent(s1, ev_fork, 0);
    k_inv<<<cdiv(np, 256), 256, 0, s1>>>(unpool, inv, np);
    k_gemm_mma<<<cdiv(np, 64), 256, GEMM_SMEM, s1>>>(px, img0h, img0l, h1, np, nullptr, nullptr);
    cudaEventRecord(ev_g0, s1);

    // s2: full-graph CSR; dinvf ready after k_write, esrcf after k_place
    cudaStreamWaitEvent(s2, ev_fork, 0);
    k_hist<<<cdiv(Ef, 256), 256, 0, s2>>>(ei + Ef, Ef, cntf);
    k_bsum<<<nbf, 256, 0, s2>>>(cntf, nf, bsf);
    k_write<<<nbf, 256, 0, s2>>>(cntf, nf, bsf, nbf, rpf, curf, dinvf);
    cudaEventRecord(ev_dinv, s2);
    k_place<<<cdiv(Ef, 256), 256, 0, s2>>>(ei, ei + Ef, Ef, curf, esrcf);
    cudaEventRecord(ev_place, s2);

    // main: pooled CSR (short)
    k_hist<<<cdiv(Ep, 256), 256>>>(pei + Ep, Ep, cntp);
    k_bsum<<<nbp, 256>>>(cntp, np, bsp);
    k_write<<<nbp, 256>>>(cntp, np, bsp, nbp, rpp, curp, dinvp);
    k_place<<<cdiv(Ep, 256), 256>>>(pei, pei + Ep, Ep, curp, esrcp);

    // conv0 gather (per-edge dinv; needs GEMM0 + pooled CSR)
    cudaStreamWaitEvent(0, ev_g0, 0);
    k_gather<<<cdiv(np, 8), 256>>>(rpp, esrcp, dinvp, h1, b0, nullptr, buf2, np);

    // conv1: compact GEMM needs only dinvf; gather1 needs esrcf too
    cudaStreamWaitEvent(0, ev_dinv, 0);
    k_gemm_mma<<<cdiv(np, 64), 256, GEMM_SMEM>>>(buf2, img1h, img1l, h2, np, dinvf, unpool);
    cudaStreamWaitEvent(0, ev_place, 0);
    k_gather_s<<<cdiv(nf, 8), 256>>>(rpf, esrcf, dinvf, h2, b1, inv, buf2, nf);

    // conv2: full GEMM with dinvf[row] epilogue scale + pre-scaled gather -> out
    k_gemm_mma<<<cdiv(nf, 64), 256, GEMM_SMEM>>>(buf2, img2h, img2l, h1, nf, dinvf, nullptr);
    k_gather_s<<<cdiv(nf, 8), 256>>>(rpf, esrcf, dinvf, h1, b2, nullptr, out, nf);
}